// round 17
// baseline (speedup 1.0000x reference)
#include <cuda_runtime.h>
#include <cuda_bf16.h>
#include <math.h>
#include <stdint.h>

// Problem constants
#define Bn   4
#define Sn   4096
#define Dn   1024
#define Hn   16
#define HDn  64
#define SEGn 64
#define NSn  64
#define NTOK (Bn*Sn)          // 16384
#define NEGV (-1.0e10f)

// ---------------------------------------------------------------------------
// Scratch (device globals)
// ---------------------------------------------------------------------------
__device__ float g_t1     [(size_t)NTOK*Dn];
__device__ float g_merged [(size_t)NTOK*Dn];     // global_merged partial
__device__ float g_joint  [(size_t)NTOK*Hn*128]; // [0:64] local masked logits

// Split-bf16 tensors (hi/lo pairs)
__device__ __nv_bfloat16 g_ahi [(size_t)NTOK*Dn];   // staging (x, t2, merged)
__device__ __nv_bfloat16 g_alo [(size_t)NTOK*Dn];
__device__ __nv_bfloat16 g_qhi [(size_t)NTOK*Dn];
__device__ __nv_bfloat16 g_qlo [(size_t)NTOK*Dn];
__device__ __nv_bfloat16 g_khi [(size_t)NTOK*Dn];
__device__ __nv_bfloat16 g_klo [(size_t)NTOK*Dn];
__device__ __nv_bfloat16 g_vhi [(size_t)NTOK*Dn];
__device__ __nv_bfloat16 g_vlo [(size_t)NTOK*Dn];
__device__ __nv_bfloat16 g_krhi[(size_t)NTOK*Dn];
__device__ __nv_bfloat16 g_krlo[(size_t)NTOK*Dn];
__device__ __nv_bfloat16 g_rahi[(size_t)NTOK*Dn];   // rowattn split
__device__ __nv_bfloat16 g_ralo[(size_t)NTOK*Dn];
__device__ __nv_bfloat16 g_phi [(size_t)NTOK*Hn*64]; // local probs split
__device__ __nv_bfloat16 g_plo [(size_t)NTOK*Hn*64];
__device__ __nv_bfloat16 g_wthi[(size_t)6*Dn*Dn];
__device__ __nv_bfloat16 g_wtlo[(size_t)6*Dn*Dn];

__device__ __forceinline__ float* cpick(float* ext, int id){
    if (id == 4) return g_t1;
    return ext;
}
__device__ __forceinline__ __nv_bfloat16* hpick(int id){
    switch(id){ case 11: return g_qhi; case 12: return g_khi;
                case 13: return g_vhi; case 14: return g_krhi; }
    return g_ahi;
}
__device__ __forceinline__ __nv_bfloat16* lpick(int id){
    switch(id){ case 11: return g_qlo; case 12: return g_klo;
                case 13: return g_vlo; case 14: return g_krlo; }
    return g_alo;
}

__device__ __forceinline__ uint32_t pack_hi(float a, float b){
    __nv_bfloat162 t(__float2bfloat16_rn(a), __float2bfloat16_rn(b));
    return *(uint32_t*)&t;
}
__device__ __forceinline__ uint32_t pack_lo(float a, float b){
    float ha = __bfloat162float(__float2bfloat16_rn(a));
    float hb = __bfloat162float(__float2bfloat16_rn(b));
    __nv_bfloat162 t(__float2bfloat16_rn(a-ha), __float2bfloat16_rn(b-hb));
    return *(uint32_t*)&t;
}
__device__ __forceinline__ void store_split4(float4 v, size_t off){
    uint2 hv, lv;
    hv.x = pack_hi(v.x,v.y); hv.y = pack_hi(v.z,v.w);
    lv.x = pack_lo(v.x,v.y); lv.y = pack_lo(v.z,v.w);
    *(uint2*)(g_ahi + off) = hv;
    *(uint2*)(g_alo + off) = lv;
}

__device__ __forceinline__ uint32_t smem_u32(const void* p){
    uint32_t a;
    asm("{ .reg .u64 t; cvta.to.shared.u64 t, %1; cvt.u32.u64 %0, t; }" : "=r"(a) : "l"(p));
    return a;
}
__device__ __forceinline__ void cp_async16(uint32_t dst, const void* src){
    asm volatile("cp.async.cg.shared.global [%0], [%1], 16;" :: "r"(dst), "l"(src) : "memory");
}
__device__ __forceinline__ void cp_commit(){
    asm volatile("cp.async.commit_group;" ::: "memory");
}
template<int N> __device__ __forceinline__ void cp_wait(){
    asm volatile("cp.async.wait_group %0;" :: "n"(N) : "memory");
}
__device__ __forceinline__ void mma16816(float* c, const uint32_t* a, const uint32_t* b){
    asm volatile("mma.sync.aligned.m16n8k16.row.col.f32.bf16.bf16.f32 "
                 "{%0,%1,%2,%3}, {%4,%5,%6,%7}, {%8,%9}, {%0,%1,%2,%3};"
                 : "+f"(c[0]), "+f"(c[1]), "+f"(c[2]), "+f"(c[3])
                 : "r"(a[0]), "r"(a[1]), "r"(a[2]), "r"(a[3]), "r"(b[0]), "r"(b[1]));
}
__device__ __forceinline__ void ldsm_x4(uint32_t* r, uint32_t addr){
    asm volatile("ldmatrix.sync.aligned.m8n8.x4.shared.b16 {%0,%1,%2,%3}, [%4];"
                 : "=r"(r[0]), "=r"(r[1]), "=r"(r[2]), "=r"(r[3]) : "r"(addr));
}
__device__ __forceinline__ void ldsm_x4_t(uint32_t* r, uint32_t addr){
    asm volatile("ldmatrix.sync.aligned.m8n8.x4.trans.shared.b16 {%0,%1,%2,%3}, [%4];"
                 : "=r"(r[0]), "=r"(r[1]), "=r"(r[2]), "=r"(r[3]) : "r"(addr));
}

// ---------------------------------------------------------------------------
// Split conversion: x fp32 -> staging (hi,lo)
// ---------------------------------------------------------------------------
__global__ void __launch_bounds__(256)
convert_act(const float* __restrict__ src)
{
    size_t i = (size_t)blockIdx.x*256 + threadIdx.x;
    float4 v = ((const float4*)src)[i];
    store_split4(v, i*4);
}

// ---------------------------------------------------------------------------
// Weight transpose+split: WT[w][n][k] = split(W[w][k][n])
// ---------------------------------------------------------------------------
__global__ void __launch_bounds__(256)
convert_wt(const float* __restrict__ W0, const float* __restrict__ W1,
           const float* __restrict__ W2, const float* __restrict__ W3,
           const float* __restrict__ W4, const float* __restrict__ W5)
{
    const float* Ws[6] = {W0,W1,W2,W3,W4,W5};
    const float* W = Ws[blockIdx.z];
    __shared__ float tile[32][33];
    int n0 = blockIdx.x*32, k0 = blockIdx.y*32;
    int tx = threadIdx.x & 31, ty = threadIdx.x >> 5;
    #pragma unroll
    for (int j = 0; j < 4; j++){
        int r = ty + j*8;
        tile[r][tx] = W[(size_t)(k0+r)*Dn + n0 + tx];
    }
    __syncthreads();
    size_t wbase = (size_t)blockIdx.z*Dn*Dn;
    #pragma unroll
    for (int j = 0; j < 4; j++){
        int r = ty + j*8;
        float a = tile[tx][r];
        __nv_bfloat16 hi = __float2bfloat16_rn(a);
        __nv_bfloat16 lo = __float2bfloat16_rn(a - __bfloat162float(hi));
        size_t o = wbase + (size_t)(n0+r)*Dn + k0 + tx;
        g_wthi[o] = hi;
        g_wtlo[o] = lo;
    }
}

// ---------------------------------------------------------------------------
// PERSISTENT HMMA GEMM (BK=32, occ 2) — 1-D grid, loops over tiles.
// Tile tg: n0=(tg&7)*128, m0=((tg>>3)&127)*128, widx-plane = tg>>10 (QKV).
// ---------------------------------------------------------------------------
#define AST  40
#define TSZB (128*AST*2)          // 10240 B per matrix
#define BUFB (4*TSZB)             // 40960 B per buffer
#define HG_SMEM (2*BUFB)          // 81920 B
#define GEMM_GRID 296

__global__ void __launch_bounds__(256,2)
hmma_gemm(int widx0, int Aid, float* Cext, int Cid0,
          const float* __restrict__ R, float alpha0, int NT)
{
    extern __shared__ char smem[];
    uint32_t sb = smem_u32(smem);
    int tid = threadIdx.x, lane = tid & 31, wid = tid >> 5;
    int wm = wid & 1, wn = wid >> 1;

    uint32_t aoff = (uint32_t)(((wm*64 + (lane&15))*AST + ((lane>>4)<<3)) * 2);
    uint32_t boff = (uint32_t)(((wn*32 + ((lane>>4)<<3) + (lane&7))*AST + (((lane>>3)&1)<<3)) * 2);

    for (int tg = blockIdx.x; tg < NT; tg += gridDim.x){
        int n0 = (tg & 7)*128;
        int m0 = ((tg >> 3) & 127)*128;
        int widx = widx0, Cid = Cid0;
        float alpha = alpha0;
        if (widx0 < 0){
            int z = tg >> 10;
            widx = z; Cid = 11 + z;
            alpha = (z == 0) ? 0.125f : 1.f;
        }

        const __nv_bfloat16* srcs[4];
        srcs[0] = (Aid ? g_rahi : g_ahi) + (size_t)m0*Dn;
        srcs[1] = (Aid ? g_ralo : g_alo) + (size_t)m0*Dn;
        srcs[2] = g_wthi + (size_t)widx*Dn*Dn + (size_t)n0*Dn;
        srcs[3] = g_wtlo + (size_t)widx*Dn*Dn + (size_t)n0*Dn;

        auto fill = [&](int c, int buf){
            int k0 = c*32;
            uint32_t base = sb + buf*BUFB;
            #pragma unroll
            for (int t = 0; t < 4; t++){
                #pragma unroll
                for (int it = 0; it < 2; it++){
                    int idx = it*256 + tid;
                    int r = idx >> 2, cc = idx & 3;
                    cp_async16(base + t*TSZB + r*(AST*2) + cc*16,
                               srcs[t] + (size_t)r*Dn + k0 + cc*8);
                }
            }
            cp_commit();
        };

        float acc[4][4][4];
        #pragma unroll
        for (int i=0;i<4;i++)
            #pragma unroll
            for (int j=0;j<4;j++)
                #pragma unroll
                for (int q=0;q<4;q++) acc[i][j][q]=0.f;

        fill(0, 0);

        for (int c = 0; c < 32; c++){
            int buf = c & 1;
            if (c < 31){ fill(c+1, buf^1); cp_wait<1>(); }
            else       { cp_wait<0>(); }
            __syncthreads();

            #pragma unroll
            for (int ks = 0; ks < 2; ks++){
                uint32_t ah[4][4], al[4][4], bh2[2][4], bl2[2][4];
                uint32_t abase = sb + buf*BUFB + aoff + (uint32_t)(ks*32);
                #pragma unroll
                for (int i=0;i<4;i++){
                    uint32_t ad = abase + i*(16*AST*2);
                    ldsm_x4(ah[i], ad);
                    ldsm_x4(al[i], ad + TSZB);
                }
                uint32_t bbase = sb + buf*BUFB + 2*TSZB + boff + (uint32_t)(ks*32);
                #pragma unroll
                for (int tp=0;tp<2;tp++){
                    uint32_t bd = bbase + tp*(16*AST*2);
                    ldsm_x4(bh2[tp], bd);
                    ldsm_x4(bl2[tp], bd + TSZB);
                }
                #pragma unroll
                for (int i = 0; i < 4; i++)
                    #pragma unroll
                    for (int j = 0; j < 4; j++){
                        const uint32_t* bh = bh2[j>>1] + (j&1)*2;
                        const uint32_t* bl = bl2[j>>1] + (j&1)*2;
                        mma16816(acc[i][j], ah[i], bh);
                        mma16816(acc[i][j], ah[i], bl);
                        mma16816(acc[i][j], al[i], bh);
                    }
            }
            __syncthreads();
        }

        if (Cid >= 11){
            __nv_bfloat16* Hi = hpick(Cid);
            __nv_bfloat16* Lo = lpick(Cid);
            #pragma unroll
            for (int i = 0; i < 4; i++){
                int row = m0 + wm*64 + i*16 + (lane>>2);
                #pragma unroll
                for (int j = 0; j < 4; j++){
                    int col = n0 + wn*32 + j*8 + 2*(lane&3);
                    size_t o0 = (size_t)row*Dn + col;
                    size_t o1 = (size_t)(row+8)*Dn + col;
                    float a0 = alpha*acc[i][j][0], a1 = alpha*acc[i][j][1];
                    float a2 = alpha*acc[i][j][2], a3 = alpha*acc[i][j][3];
                    *(uint32_t*)(Hi + o0) = pack_hi(a0, a1);
                    *(uint32_t*)(Lo + o0) = pack_lo(a0, a1);
                    *(uint32_t*)(Hi + o1) = pack_hi(a2, a3);
                    *(uint32_t*)(Lo + o1) = pack_lo(a2, a3);
                }
            }
        } else {
            float* C = cpick(Cext, Cid);
            #pragma unroll
            for (int i = 0; i < 4; i++){
                int row = m0 + wm*64 + i*16 + (lane>>2);
                #pragma unroll
                for (int j = 0; j < 4; j++){
                    int col = n0 + wn*32 + j*8 + 2*(lane&3);
                    size_t o0 = (size_t)row*Dn + col;
                    size_t o1 = (size_t)(row+8)*Dn + col;
                    float2 v0, v1;
                    v0.x = alpha*acc[i][j][0]; v0.y = alpha*acc[i][j][1];
                    v1.x = alpha*acc[i][j][2]; v1.y = alpha*acc[i][j][3];
                    if (R){
                        float2 r0 = *(const float2*)(R + o0);
                        float2 r1 = *(const float2*)(R + o1);
                        v0.x += r0.x; v0.y += r0.y; v1.x += r1.x; v1.y += r1.y;
                    }
                    *(float2*)(C + o0) = v0;
                    *(float2*)(C + o1) = v1;
                }
            }
        }
        __syncthreads();
    }
}

// ---------------------------------------------------------------------------
// Attention tiles: KST=72 (144 B rows, ldmatrix conflict-free, 16B aligned)
// ---------------------------------------------------------------------------
#define KST 72
#define TILEB (64*KST*2)               // 9216 B per tile
#define LA_SMEM (6*TILEB + 1024)       // 56320 B

#define ATT_AOFF(lane, r0)  ((uint32_t)((((r0) + ((lane)&15))*KST + (((lane)>>4)<<3))*2))
#define ATT_BOFF(lane, n0)  ((uint32_t)(((((n0) + (((lane)>>4)<<3) + ((lane)&7))*KST) + ((((lane)>>3)&1)<<3))*2))
#define ATT_TOFF(lane, n0)  ((uint32_t)((((((lane)>>3)&1)*8 + ((lane)&7))*KST + (n0) + (((lane)>>4)<<3))*2))

// ---------------------------------------------------------------------------
// MMA local attention per (h, seg, b)
// ---------------------------------------------------------------------------
__global__ void __launch_bounds__(256)
local_attn_kernel()
{
    extern __shared__ __nv_bfloat16 bsm[];
    __nv_bfloat16* qh = bsm;            // reused for P hi/lo
    __nv_bfloat16* ql = bsm + TILEB/2;
    float* red = (float*)((char*)bsm + 6*TILEB);

    int h = blockIdx.x, seg = blockIdx.y, b = blockIdx.z;
    int tid = threadIdx.x, lane = tid & 31, wid = tid >> 5;
    int g = lane >> 2, c = lane & 3;
    size_t tok0 = ((size_t)b*NSn + seg)*SEGn;
    size_t hb = tok0*Dn + h*HDn;
    uint32_t sbB = smem_u32(bsm);

    const __nv_bfloat16* srcs[6] = {g_qhi+hb, g_qlo+hb, g_khi+hb, g_klo+hb, g_vhi+hb, g_vlo+hb};
    #pragma unroll
    for (int t = 0; t < 6; t++){
        #pragma unroll
        for (int it = 0; it < 2; it++){
            int idx = it*256 + tid;
            int r = idx >> 3, cc = idx & 7;
            cp_async16(sbB + t*TILEB + r*(KST*2) + cc*16,
                       srcs[t] + (size_t)r*Dn + cc*8);
        }
    }
    cp_commit(); cp_wait<0>();
    __syncthreads();

    int mband = wid & 3, nhalf = wid >> 2;
    int r0 = mband*16, n0 = nhalf*32;
    int rA = r0 + g, rB = rA + 8;
    uint32_t aoff = ATT_AOFF(lane, r0);
    uint32_t boff = ATT_BOFF(lane, n0);
    uint32_t toff = ATT_TOFF(lane, n0);

    // --- S = q @ k^T ---
    float accS[4][4];
    #pragma unroll
    for (int t=0;t<4;t++)
        #pragma unroll
        for (int q2=0;q2<4;q2++) accS[t][q2]=0.f;

    #pragma unroll
    for (int kk = 0; kk < 4; kk++){
        uint32_t ah[4], al[4], bh2[2][4], bl2[2][4];
        uint32_t ad = sbB + aoff + kk*32;
        ldsm_x4(ah, ad);
        ldsm_x4(al, ad + TILEB);
        uint32_t bd = sbB + 2*TILEB + boff + kk*32;
        ldsm_x4(bh2[0], bd);
        ldsm_x4(bl2[0], bd + TILEB);
        ldsm_x4(bh2[1], bd + 16*KST*2);
        ldsm_x4(bl2[1], bd + 16*KST*2 + TILEB);
        #pragma unroll
        for (int t = 0; t < 4; t++){
            const uint32_t* bh = bh2[t>>1] + (t&1)*2;
            const uint32_t* bl = bl2[t>>1] + (t&1)*2;
            mma16816(accS[t], ah, bh);
            mma16816(accS[t], ah, bl);
            mma16816(accS[t], al, bh);
        }
    }

    // masked logits -> g_joint
    size_t jbA = ((tok0 + rA)*Hn + h)*128;
    size_t jbB = ((tok0 + rB)*Hn + h)*128;
    #pragma unroll
    for (int t = 0; t < 4; t++){
        int col0 = n0 + t*8 + 2*c;
        float2 w0, w1;
        w0.x = accS[t][0] + (rA < col0   ? NEGV : 0.f);
        w0.y = accS[t][1] + (rA < col0+1 ? NEGV : 0.f);
        w1.x = accS[t][2] + (rB < col0   ? NEGV : 0.f);
        w1.y = accS[t][3] + (rB < col0+1 ? NEGV : 0.f);
        *(float2*)(g_joint + jbA + col0) = w0;
        *(float2*)(g_joint + jbB + col0) = w1;
    }

    // --- unmasked softmax ---
    float mA = -1e30f, mB = -1e30f;
    #pragma unroll
    for (int t=0;t<4;t++){
        mA = fmaxf(mA, fmaxf(accS[t][0], accS[t][1]));
        mB = fmaxf(mB, fmaxf(accS[t][2], accS[t][3]));
    }
    mA = fmaxf(mA, __shfl_xor_sync(0xffffffffu, mA, 1));
    mA = fmaxf(mA, __shfl_xor_sync(0xffffffffu, mA, 2));
    mB = fmaxf(mB, __shfl_xor_sync(0xffffffffu, mB, 1));
    mB = fmaxf(mB, __shfl_xor_sync(0xffffffffu, mB, 2));
    if (c == 0){ red[nhalf*64 + rA] = mA; red[nhalf*64 + rB] = mB; }
    __syncthreads();
    float mmA = fmaxf(red[rA], red[64+rA]);
    float mmB = fmaxf(red[rB], red[64+rB]);

    float p[4][4];
    float sA = 0.f, sB = 0.f;
    #pragma unroll
    for (int t=0;t<4;t++){
        p[t][0] = __expf(accS[t][0]-mmA); p[t][1] = __expf(accS[t][1]-mmA);
        p[t][2] = __expf(accS[t][2]-mmB); p[t][3] = __expf(accS[t][3]-mmB);
        sA += p[t][0]+p[t][1]; sB += p[t][2]+p[t][3];
    }
    sA += __shfl_xor_sync(0xffffffffu, sA, 1);
    sA += __shfl_xor_sync(0xffffffffu, sA, 2);
    sB += __shfl_xor_sync(0xffffffffu, sB, 1);
    sB += __shfl_xor_sync(0xffffffffu, sB, 2);
    if (c == 0){ red[128 + nhalf*64 + rA] = sA; red[128 + nhalf*64 + rB] = sB; }
    __syncthreads();
    float invA = 1.f/(red[128+rA] + red[128+64+rA]);
    float invB = 1.f/(red[128+rB] + red[128+64+rB]);

    // unnormalized P (split) into q region
    #pragma unroll
    for (int t = 0; t < 4; t++){
        int col0 = n0 + t*8 + 2*c;
        *(uint32_t*)(qh + rA*KST + col0) = pack_hi(p[t][0], p[t][1]);
        *(uint32_t*)(ql + rA*KST + col0) = pack_lo(p[t][0], p[t][1]);
        *(uint32_t*)(qh + rB*KST + col0) = pack_hi(p[t][2], p[t][3]);
        *(uint32_t*)(ql + rB*KST + col0) = pack_lo(p[t][2], p[t][3]);
    }
    __syncthreads();

    // --- O = P @ V (trans-B on row-major v tiles) ---
    float accO[4][4];
    #pragma unroll
    for (int t=0;t<4;t++)
        #pragma unroll
        for (int q2=0;q2<4;q2++) accO[t][q2]=0.f;

    #pragma unroll
    for (int kk = 0; kk < 4; kk++){
        uint32_t ah[4], al[4], bh2[2][4], bl2[2][4];
        uint32_t ad = sbB + aoff + kk*32;
        ldsm_x4(ah, ad);
        ldsm_x4(al, ad + TILEB);
        uint32_t bd = sbB + 4*TILEB + toff + kk*(16*KST*2);
        ldsm_x4_t(bh2[0], bd);
        ldsm_x4_t(bl2[0], bd + TILEB);
        ldsm_x4_t(bh2[1], bd + 16*2);
        ldsm_x4_t(bl2[1], bd + 16*2 + TILEB);
        #pragma unroll
        for (int t = 0; t < 4; t++){
            const uint32_t* bh = bh2[t>>1] + (t&1)*2;
            const uint32_t* bl = bl2[t>>1] + (t&1)*2;
            mma16816(accO[t], ah, bh);
            mma16816(accO[t], ah, bl);
            mma16816(accO[t], al, bh);
        }
    }

    // rowattn = O * inv, split-only store
    #pragma unroll
    for (int t = 0; t < 4; t++){
        int col0 = n0 + t*8 + 2*c;
        size_t oA = (tok0+rA)*Dn + h*HDn + col0;
        size_t oB = (tok0+rB)*Dn + h*HDn + col0;
        float a0 = accO[t][0]*invA, a1 = accO[t][1]*invA;
        float a2 = accO[t][2]*invB, a3 = accO[t][3]*invB;
        *(uint32_t*)(g_rahi + oA) = pack_hi(a0, a1);
        *(uint32_t*)(g_ralo + oA) = pack_lo(a0, a1);
        *(uint32_t*)(g_rahi + oB) = pack_hi(a2, a3);
        *(uint32_t*)(g_ralo + oB) = pack_lo(a2, a3);
    }
}

// ---------------------------------------------------------------------------
// LayerNorm: writes staging split directly
// ---------------------------------------------------------------------------
__global__ void __launch_bounds__(256)
ln_kernel(const float* __restrict__ scale, const float* __restrict__ bias)
{
    size_t row = blockIdx.x;
    int tid = threadIdx.x;
    float4 v = ((const float4*)(g_t1 + row*Dn))[tid];
    float s  = v.x+v.y+v.z+v.w;
    float ss = v.x*v.x+v.y*v.y+v.z*v.z+v.w*v.w;
    #pragma unroll
    for (int o=16;o;o>>=1){
        s  += __shfl_xor_sync(0xffffffffu, s, o);
        ss += __shfl_xor_sync(0xffffffffu, ss, o);
    }
    __shared__ float sh[16];
    int w = tid>>5, lane = tid&31;
    if (lane==0){ sh[w]=s; sh[8+w]=ss; }
    __syncthreads();
    if (tid==0){
        float a=0.f,b2=0.f;
        #pragma unroll
        for (int i=0;i<8;i++){ a+=sh[i]; b2+=sh[8+i]; }
        float mu  = a*(1.f/Dn);
        float var = b2*(1.f/Dn) - mu*mu;
        sh[0]=mu; sh[1]=rsqrtf(var + 1e-6f);
    }
    __syncthreads();
    float mu = sh[0], rstd = sh[1];
    float4 sc = ((const float4*)scale)[tid];
    float4 bi = ((const float4*)bias)[tid];
    float4 o4;
    o4.x=(v.x-mu)*rstd*sc.x+bi.x;
    o4.y=(v.y-mu)*rstd*sc.y+bi.y;
    o4.z=(v.z-mu)*rstd*sc.z+bi.z;
    o4.w=(v.w-mu)*rstd*sc.w+bi.w;
    store_split4(o4, row*Dn + tid*4);
}

// ---------------------------------------------------------------------------
// MMA FUSED global logits + joint softmax + global merge, per (h, l, b)
// ---------------------------------------------------------------------------
__global__ void __launch_bounds__(256)
global_fused_kernel()
{
    extern __shared__ __nv_bfloat16 bsm[];
    __nv_bfloat16* qh = bsm;            // reused for gatt hi/lo
    __nv_bfloat16* ql = bsm + TILEB/2;
    float* red = (float*)((char*)bsm + 6*TILEB);

    int h = blockIdx.x, l = blockIdx.y, b = blockIdx.z;
    int tid = threadIdx.x, lane = tid & 31, wid = tid >> 5;
    int g = lane >> 2, c = lane & 3;
    uint32_t sbB = smem_u32(bsm);

    const __nv_bfloat16* bases[6] = {g_qhi, g_qlo, g_krhi, g_krlo, g_rahi, g_ralo};
    #pragma unroll
    for (int t = 0; t < 6; t++){
        #pragma unroll
        for (int it = 0; it < 2; it++){
            int idx = it*256 + tid;
            int r = idx >> 3, cc = idx & 7;
            size_t src = (((size_t)b*NSn + r)*SEGn + l)*Dn + h*HDn + cc*8;
            cp_async16(sbB + t*TILEB + r*(KST*2) + cc*16, bases[t] + src);
        }
    }
    cp_commit(); cp_wait<0>();
    __syncthreads();

    int mband = wid & 3, nhalf = wid >> 2;
    int n0 = nhalf*32;
    int rA = mband*16 + g, rB = rA + 8;   // qseg rows
    uint32_t aoff = ATT_AOFF(lane, mband*16);
    uint32_t boff = ATT_BOFF(lane, n0);
    uint32_t toff = ATT_TOFF(lane, n0);

    // --- S = q @ krow^T ---
    float accS[4][4];
    #pragma unroll
    for (int t=0;t<4;t++)
        #pragma unroll
        for (int q2=0;q2<4;q2++) accS[t][q2]=0.f;

    #pragma unroll
    for (int kk = 0; kk < 4; kk++){
        uint32_t ah[4], al[4], bh2[2][4], bl2[2][4];
        uint32_t ad = sbB + aoff + kk*32;
        ldsm_x4(ah, ad);
        ldsm_x4(al, ad + TILEB);
        uint32_t bd = sbB + 2*TILEB + boff + kk*32;
        ldsm_x4(bh2[0], bd);
        ldsm_x4(bl2[0], bd + TILEB);
        ldsm_x4(bh2[1], bd + 16*KST*2);
        ldsm_x4(bl2[1], bd + 16*KST*2 + TILEB);
        #pragma unroll
        for (int t = 0; t < 4; t++){
            const uint32_t* bh = bh2[t>>1] + (t&1)*2;
            const uint32_t* bl = bl2[t>>1] + (t&1)*2;
            mma16816(accS[t], ah, bh);
            mma16816(accS[t], ah, bl);
            mma16816(accS[t], al, bh);
        }
    }

    // mask qseg <= kseg
    #pragma unroll
    for (int t = 0; t < 4; t++){
        int col0 = n0 + t*8 + 2*c;
        accS[t][0] += (rA <= col0   ? NEGV : 0.f);
        accS[t][1] += (rA <= col0+1 ? NEGV : 0.f);
        accS[t][2] += (rB <= col0   ? NEGV : 0.f);
        accS[t][3] += (rB <= col0+1 ? NEGV : 0.f);
    }

    size_t tA = ((size_t)b*NSn + rA)*SEGn + l;
    size_t tB = ((size_t)b*NSn + rB)*SEGn + l;
    size_t jbA = (tA*Hn + h)*128;
    size_t jbB = (tB*Hn + h)*128;
    float2 locA[4], locB[4];
    #pragma unroll
    for (int t = 0; t < 4; t++){
        int col0 = n0 + t*8 + 2*c;
        locA[t] = *(const float2*)(g_joint + jbA + col0);
        locB[t] = *(const float2*)(g_joint + jbB + col0);
    }

    // --- joint softmax ---
    float mA = -1e30f, mB = -1e30f;
    #pragma unroll
    for (int t=0;t<4;t++){
        mA = fmaxf(mA, fmaxf(fmaxf(accS[t][0], accS[t][1]), fmaxf(locA[t].x, locA[t].y)));
        mB = fmaxf(mB, fmaxf(fmaxf(accS[t][2], accS[t][3]), fmaxf(locB[t].x, locB[t].y)));
    }
    mA = fmaxf(mA, __shfl_xor_sync(0xffffffffu, mA, 1));
    mA = fmaxf(mA, __shfl_xor_sync(0xffffffffu, mA, 2));
    mB = fmaxf(mB, __shfl_xor_sync(0xffffffffu, mB, 1));
    mB = fmaxf(mB, __shfl_xor_sync(0xffffffffu, mB, 2));
    if (c == 0){ red[nhalf*64 + rA] = mA; red[nhalf*64 + rB] = mB; }
    __syncthreads();
    float mmA = fmaxf(red[rA], red[64+rA]);
    float mmB = fmaxf(red[rB], red[64+rB]);

    float p[4][4];
    float sA = 0.f, sB = 0.f;
    #pragma unroll
    for (int t=0;t<4;t++){
        p[t][0] = __expf(accS[t][0]-mmA); p[t][1] = __expf(accS[t][1]-mmA);
        p[t][2] = __expf(accS[t][2]-mmB); p[t][3] = __expf(accS[t][3]-mmB);
        locA[t].x = __expf(locA[t].x-mmA); locA[t].y = __expf(locA[t].y-mmA);
        locB[t].x = __expf(locB[t].x-mmB); locB[t].y = __expf(locB[t].y-mmB);
        sA += p[t][0]+p[t][1] + locA[t].x+locA[t].y;
        sB += p[t][2]+p[t][3] + locB[t].x+locB[t].y;
    }
    sA += __shfl_xor_sync(0xffffffffu, sA, 1);
    sA += __shfl_xor_sync(0xffffffffu, sA, 2);
    sB += __shfl_xor_sync(0xffffffffu, sB, 1);
    sB += __shfl_xor_sync(0xffffffffu, sB, 2);
    if (c == 0){ red[128 + nhalf*64 + rA] = sA; red[128 + nhalf*64 + rB] = sB; }
    __syncthreads();
    float invA = 1.f/(red[128+rA] + red[128+64+rA]);
    float invB = 1.f/(red[128+rB] + red[128+64+rB]);

    // normalized local probs -> split buffers (consumed by local_merged)
    size_t pbA = (tA*Hn + h)*64;
    size_t pbB = (tB*Hn + h)*64;
    #pragma unroll
    for (int t = 0; t < 4; t++){
        int col0 = n0 + t*8 + 2*c;
        float a0 = locA[t].x*invA, a1 = locA[t].y*invA;
        float b0 = locB[t].x*invB, b1 = locB[t].y*invB;
        *(uint32_t*)(g_phi + pbA + col0) = pack_hi(a0, a1);
        *(uint32_t*)(g_plo + pbA + col0) = pack_lo(a0, a1);
        *(uint32_t*)(g_phi + pbB + col0) = pack_hi(b0, b1);
        *(uint32_t*)(g_plo + pbB + col0) = pack_lo(b0, b1);
    }

    // normalized gatt (split) into q region
    #pragma unroll
    for (int t = 0; t < 4; t++){
        int col0 = n0 + t*8 + 2*c;
        *(uint32_t*)(qh + rA*KST + col0) = pack_hi(p[t][0]*invA, p[t][1]*invA);
        *(uint32_t*)(ql + rA*KST + col0) = pack_lo(p[t][0]*invA, p[t][1]*invA);
        *(uint32_t*)(qh + rB*KST + col0) = pack_hi(p[t][2]*invB, p[t][3]*invB);
        *(uint32_t*)(ql + rB*KST + col0) = pack_lo(p[t][2]*invB, p[t][3]*invB);
    }
    __syncthreads();

    // --- O = gatt @ rowattn (trans-B on row-major ra tiles) ---
    float accO[4][4];
    #pragma unroll
    for (int t=0;t<4;t++)
        #pragma unroll
        for (int q2=0;q2<4;q2++) accO[t][q2]=0.f;

    #pragma unroll
    for (int kk = 0; kk < 4; kk++){
        uint32_t ah[4], al[4], bh2[2][4], bl2[2][4];
        uint32_t ad = sbB + aoff + kk*32;
        ldsm_x4(ah, ad);
        ldsm_x4(al, ad + TILEB);
        uint32_t bd = sbB + 4*TILEB + toff + kk*(16*KST*2);
        ldsm_x4_t(bh2[0], bd);
        ldsm_x4_t(bl2[0], bd + TILEB);
        ldsm_x4_t(bh2[1], bd + 16*2);
        ldsm_x4_t(bl2[1], bd + 16*2 + TILEB);
        #pragma unroll
        for (int t = 0; t < 4; t++){
            const uint32_t* bh = bh2[t>>1] + (t&1)*2;
            const uint32_t* bl = bl2[t>>1] + (t&1)*2;
            mma16816(accO[t], ah, bh);
            mma16816(accO[t], ah, bl);
            mma16816(accO[t], al, bh);
        }
    }

    #pragma unroll
    for (int t = 0; t < 4; t++){
        int col0 = n0 + t*8 + 2*c;
        size_t oA = tA*Dn + h*HDn + col0;
        size_t oB = tB*Dn + h*HDn + col0;
        *(float2*)(g_merged + oA) = make_float2(accO[t][0], accO[t][1]);
        *(float2*)(g_merged + oB) = make_float2(accO[t][2], accO[t][3]);
    }
}

// ---------------------------------------------------------------------------
// MMA local_merged finalizer per (h, seg, b): all operands split via cp.async.
// Writes staging split for out GEMM.
// ---------------------------------------------------------------------------
#define LM_SMEM (4*TILEB)
__global__ void __launch_bounds__(256)
local_merged_kernel()
{
    extern __shared__ __nv_bfloat16 bsm[];

    int h = blockIdx.x, seg = blockIdx.y, b = blockIdx.z;
    int tid = threadIdx.x, lane = tid & 31, wid = tid >> 5;
    int g = lane >> 2, c = lane & 3;
    size_t tok0 = ((size_t)b*NSn + seg)*SEGn;
    size_t hb = tok0*Dn + h*HDn;
    size_t pb = (tok0*Hn + h)*64;
    uint32_t sbB = smem_u32(bsm);

    // tiles: 0=phi 1=plo 2=vhi 3=vlo
    #pragma unroll
    for (int it = 0; it < 2; it++){
        int idx = it*256 + tid;
        int r = idx >> 3, cc = idx & 7;
        cp_async16(sbB + 0*TILEB + r*(KST*2) + cc*16, g_phi + pb + (size_t)r*(Hn*64) + cc*8);
        cp_async16(sbB + 1*TILEB + r*(KST*2) + cc*16, g_plo + pb + (size_t)r*(Hn*64) + cc*8);
        cp_async16(sbB + 2*TILEB + r*(KST*2) + cc*16, g_vhi + hb + (size_t)r*Dn + cc*8);
        cp_async16(sbB + 3*TILEB + r*(KST*2) + cc*16, g_vlo + hb + (size_t)r*Dn + cc*8);
    }
    cp_commit(); cp_wait<0>();
    __syncthreads();

    int mband = wid & 3, nhalf = wid >> 2;
    int r0 = mband*16, n0 = nhalf*32;
    int rA = r0 + g, rB = rA + 8;
    uint32_t aoff = ATT_AOFF(lane, r0);
    uint32_t toff = ATT_TOFF(lane, n0);

    float accO[4][4];
    #pragma unroll
    for (int t=0;t<4;t++)
        #pragma unroll
        for (int q2=0;q2<4;q2++) accO[t][q2]=0.f;

    #pragma unroll
    for (int kk = 0; kk < 4; kk++){
        uint32_t ah[4], al[4], bh2[2][4], bl2[2][4];
        uint32_t ad = sbB + aoff + kk*32;
        ldsm_x4(ah, ad);
        ldsm_x4(al, ad + TILEB);
        uint32_t bd = sbB + 2*TILEB + toff + kk*(16*KST*2);
        ldsm_x4_t(bh2[0], bd);
        ldsm_x4_t(bl2[0], bd + TILEB);
        ldsm_x4_t(bh2[1], bd + 16*2);
        ldsm_x4_t(bl2[1], bd + 16*2 + TILEB);
        #pragma unroll
        for (int t = 0; t < 4; t++){
            const uint32_t* bh = bh2[t>>1] + (t&1)*2;
            const uint32_t* bl = bl2[t>>1] + (t&1)*2;
            mma16816(accO[t], ah, bh);
            mma16816(accO[t], ah, bl);
            mma16816(accO[t], al, bh);
        }
    }

    #pragma unroll
    for (int t = 0; t < 4; t++){
        int col0 = n0 + t*8 + 2*c;
        size_t oA = (tok0+rA)*Dn + h*HDn + col0;
        size_t oB = (tok0+rB)*Dn + h*HDn + col0;
        float2 mA = *(const float2*)(g_merged + oA);
        float2 mB = *(const float2*)(g_merged + oB);
        float a0 = mA.x + accO[t][0], a1 = mA.y + accO[t][1];
        float a2 = mB.x + accO[t][2], a3 = mB.y + accO[t][3];
        *(uint32_t*)(g_ahi + oA) = pack_hi(a0, a1);
        *(uint32_t*)(g_alo + oA) = pack_lo(a0, a1);
        *(uint32_t*)(g_ahi + oB) = pack_hi(a2, a3);
        *(uint32_t*)(g_alo + oB) = pack_lo(a2, a3);
    }
}

// ---------------------------------------------------------------------------
// Launch
// ---------------------------------------------------------------------------
extern "C" void kernel_launch(void* const* d_in, const int* in_sizes, int n_in,
                              void* d_out, int out_size)
{
    const float* x    = (const float*)d_in[0];
    const float* Wq   = (const float*)d_in[1];
    const float* Wk   = (const float*)d_in[2];
    const float* Wv   = (const float*)d_in[3];
    const float* Wro  = (const float*)d_in[4];
    const float* lns  = (const float*)d_in[5];
    const float* lnb  = (const float*)d_in[6];
    const float* Wk2  = (const float*)d_in[7];
    const float* Wout = (const float*)d_in[8];
    float* out = (float*)d_out;

    cudaFuncSetAttribute(local_attn_kernel,
                         cudaFuncAttributeMaxDynamicSharedMemorySize, LA_SMEM);
    cudaFuncSetAttribute(global_fused_kernel,
                         cudaFuncAttributeMaxDynamicSharedMemorySize, LA_SMEM);
    cudaFuncSetAttribute(local_merged_kernel,
                         cudaFuncAttributeMaxDynamicSharedMemorySize, LM_SMEM);
    cudaFuncSetAttribute(hmma_gemm,
                         cudaFuncAttributeMaxDynamicSharedMemorySize, HG_SMEM);

    dim3 ga(Hn, NSn, Bn);
    dim3 gl(Hn, SEGn, Bn);
    const int ACT_BLKS = (NTOK*Dn/4)/256;

    convert_wt<<<dim3(32,32,6),256>>>(Wq, Wk, Wv, Wro, Wk2, Wout);

    convert_act<<<ACT_BLKS,256>>>(x);
    hmma_gemm<<<GEMM_GRID,256,HG_SMEM>>>(-1, 0, nullptr, 0, nullptr, 0.f, 3072); // q,k,v

    local_attn_kernel<<<ga,256,LA_SMEM>>>();

    hmma_gemm<<<GEMM_GRID,256,HG_SMEM>>>(3, 1, nullptr, 4, x, 1.f, 1024);  // t1
    ln_kernel<<<NTOK,256>>>(lns, lnb);
    hmma_gemm<<<GEMM_GRID,256,HG_SMEM>>>(4, 0, nullptr, 14, nullptr, 1.f, 1024); // krow

    global_fused_kernel<<<gl,256,LA_SMEM>>>();
    local_merged_kernel<<<ga,256,LM_SMEM>>>();

    hmma_gemm<<<GEMM_GRID,256,HG_SMEM>>>(5, 0, out, 0, nullptr, 1.f, 1024); // output
}